// round 16
// baseline (speedup 1.0000x reference)
#include <cuda_runtime.h>
#include <cuda_fp16.h>
#include <stdint.h>

#define T_TOK  4096
#define HDIM   2048
#define NEXP   32
#define IDIM   1024
#define SIDIM  2048
#define TOPK   8
#define NGRP   8
#define TOPKG  4
#define NASSIGN (T_TOK * TOPK)
#define MAXTILES 288

// ---- GEMM tiling: BM=128, BN=128, BK=64, 3-stage cp.async ----
#define SMS  72
#define SBUF (128 * SMS)
#define NSTG 3
#define STGB (SBUF * 2)
#define SMEMB (NSTG * 2 * STGB)

// ---- device scratch (~528 MB total) ----
__device__ int   g_cnt[NEXP];
__device__ int   g_off[NEXP];
__device__ int   g_ntiles;
__device__ int   g_tile_e[MAXTILES];
__device__ int   g_tile_m[MAXTILES];
__device__ int   g_assign_e[NASSIGN];
__device__ int   g_assign_rank[NASSIGN];
__device__ float g_assign_w[NASSIGN];
__device__ int   g_perm_token[NASSIGN];
__device__ float g_perm_w[NASSIGN];
__device__ int   g_tok_pos[NASSIGN];
__device__ __align__(256) __half g_h_routed[(size_t)NASSIGN * IDIM];
__device__ __align__(256) __half g_h_shared[(size_t)T_TOK * SIDIM];
// g_y: phase 1 = f16 routed gate/up weights [E][2I][H] (256MiB, consumed by
// gemm0); phase 2 = second half holds f16 per-assignment outputs o16
// [NASSIGN][H] (written by gemm3 strictly after gemm0 on the same stream).
__device__ __align__(256) float  g_y[(size_t)NASSIGN * HDIM];
__device__ __align__(256) __half g_x16[(size_t)T_TOK * HDIM];
__device__ __align__(256) __half g_sgu16[(size_t)HDIM * 2 * SIDIM];
__device__ __align__(256) __half g_sd16[(size_t)SIDIM * HDIM];
__device__ __align__(256) __half g_wd16[(size_t)NEXP * IDIM * HDIM];   // new: own buffer

__device__ __forceinline__ void mma16816(float* C, const uint32_t* A, const uint32_t* B) {
    asm volatile(
        "mma.sync.aligned.m16n8k16.row.col.f32.f16.f16.f32 "
        "{%0,%1,%2,%3},{%4,%5,%6,%7},{%8,%9},{%0,%1,%2,%3};\n"
        : "+f"(C[0]), "+f"(C[1]), "+f"(C[2]), "+f"(C[3])
        : "r"(A[0]), "r"(A[1]), "r"(A[2]), "r"(A[3]), "r"(B[0]), "r"(B[1]));
}
__device__ __forceinline__ void ldsm4(uint32_t* r, uint32_t addr) {
    asm volatile("ldmatrix.sync.aligned.m8n8.x4.shared.b16 {%0,%1,%2,%3}, [%4];\n"
        : "=r"(r[0]), "=r"(r[1]), "=r"(r[2]), "=r"(r[3]) : "r"(addr));
}
__device__ __forceinline__ void cp16(uint32_t dst, const void* src) {
    asm volatile("cp.async.cg.shared.global [%0], [%1], 16;\n" :: "r"(dst), "l"(src));
}
__device__ __forceinline__ void cp_commit() {
    asm volatile("cp.async.commit_group;\n");
}
template <int N>
__device__ __forceinline__ void cp_wait() {
    asm volatile("cp.async.wait_group %0;\n" :: "n"(N));
}
__device__ __forceinline__ float siluf(float x) { return x / (1.f + __expf(-x)); }

// ---------------- small kernels (verbatim from passing R15) ----------------
__global__ void k_zero() { if (threadIdx.x < NEXP) g_cnt[threadIdx.x] = 0; }

__global__ void __launch_bounds__(512) k_route(const float* __restrict__ X,
                                               const float* __restrict__ GW,
                                               const float* __restrict__ bias) {
    __shared__ float xs[16][128];
    __shared__ float gws[128][32];
    const int tid = threadIdx.x, lane = tid & 31, warp = tid >> 5;
    const int t0 = blockIdx.x * 16;
    float logit = 0.f;
    for (int h0 = 0; h0 < HDIM; h0 += 128) {
        {
            int r = tid >> 5, c = (tid & 31) * 4;
            *(float4*)&xs[r][c] = *(const float4*)&X[(size_t)(t0 + r) * HDIM + h0 + c];
        }
        #pragma unroll
        for (int i = 0; i < 2; i++) {
            int id = tid + i * 512;
            int r = id >> 3, c = (id & 7) * 4;
            *(float4*)&gws[r][c] = *(const float4*)&GW[(size_t)(h0 + r) * NEXP + c];
        }
        __syncthreads();
        #pragma unroll 4
        for (int h = 0; h < 128; h++)
            logit = fmaf(xs[warp][h], gws[h][lane], logit);
        {
            int r = tid >> 5, c = (tid & 31) * 4;
            float4 v = *(const float4*)&xs[r][c];
            __half2* d = (__half2*)&g_x16[(size_t)(t0 + r) * HDIM + h0 + c];
            d[0] = __floats2half2_rn(v.x, v.y);
            d[1] = __floats2half2_rn(v.z, v.w);
        }
        __syncthreads();
    }
    float score = 1.f / (1.f + expf(-logit));
    float sc    = score + bias[lane];
    int base = lane & ~3;
    float v0 = __shfl_sync(0xffffffffu, sc, base);
    float v1 = __shfl_sync(0xffffffffu, sc, base + 1);
    float v2 = __shfl_sync(0xffffffffu, sc, base + 2);
    float v3 = __shfl_sync(0xffffffffu, sc, base + 3);
    float lo1 = fminf(v0, v1), hi1 = fmaxf(v0, v1);
    float lo2 = fminf(v2, v3), hi2 = fmaxf(v2, v3);
    float gs = (hi1 >= hi2) ? hi1 + fmaxf(lo1, hi2) : hi2 + fmaxf(lo2, hi1);
    float g8[NGRP];
    #pragma unroll
    for (int g = 0; g < NGRP; g++) g8[g] = __shfl_sync(0xffffffffu, gs, g * 4);
    unsigned gmask = 0;
    #pragma unroll
    for (int it = 0; it < TOPKG; it++) {
        int bi = -1; float bv = -1e30f;
        #pragma unroll
        for (int g = 0; g < NGRP; g++)
            if (!((gmask >> g) & 1u) && g8[g] > bv) { bv = g8[g]; bi = g; }
        gmask |= 1u << bi;
    }
    float masked = ((gmask >> (lane >> 2)) & 1u) ? sc : -1e30f;
    int ids[TOPK]; float ws[TOPK]; float wsum = 0.f;
    #pragma unroll
    for (int k = 0; k < TOPK; k++) {
        float v = masked; int ii = lane;
        #pragma unroll
        for (int o = 16; o > 0; o >>= 1) {
            float ov = __shfl_xor_sync(0xffffffffu, v, o);
            int   oi = __shfl_xor_sync(0xffffffffu, ii, o);
            if (ov > v || (ov == v && oi < ii)) { v = ov; ii = oi; }
        }
        ids[k] = ii;
        float w = __shfl_sync(0xffffffffu, score, ii);
        ws[k] = w; wsum += w;
        if (lane == ii) masked = -1e30f;
    }
    float inv = 1.f / (wsum + 1e-20f);
    const int t = t0 + warp;
    #pragma unroll
    for (int k = 0; k < TOPK; k++) {
        if (lane == k) {
            int es = ids[k];
            int r = atomicAdd(&g_cnt[es], 1);
            int ai = t * TOPK + k;
            g_assign_e[ai] = es; g_assign_rank[ai] = r;
            g_assign_w[ai] = ws[k] * inv;
        }
    }
}

__global__ void k_scan() {
    if (threadIdx.x == 0) {
        int s = 0, tt = 0;
        for (int e = 0; e < NEXP; e++) {
            g_off[e] = s;
            int c = g_cnt[e]; s += c;
            int nt = (c + 127) / 128;
            for (int i = 0; i < nt; i++) { g_tile_e[tt] = e; g_tile_m[tt] = i * 128; tt++; }
        }
        g_ntiles = tt;
    }
}

__global__ void k_perm() {
    int i = blockIdx.x * 256 + threadIdx.x;
    if (i >= NASSIGN) return;
    int e = g_assign_e[i];
    int pos = g_off[e] + g_assign_rank[i];
    g_perm_token[pos] = i >> 3;
    g_perm_w[pos] = g_assign_w[i] * 2.5f;
    g_tok_pos[i] = pos;
}

// transpose+convert: f32 [K][N] -> f16 [N'][K]; N' gate/up-interleaved if INTER.
// DST: 0 = g_y (wgu), 1 = g_sgu16, 2 = g_sd16, 3 = g_wd16.
template <bool INTER, int DST>
__global__ void k_t(const float* __restrict__ in, int K, int N, int I) {
    __shared__ float t[32][33];
    __half* outg = (DST == 0) ? (__half*)g_y
                 : (DST == 1) ? g_sgu16
                 : (DST == 2) ? g_sd16 : g_wd16;
    const float* ip = in + (size_t)blockIdx.z * K * N;
    __half* op = outg + (size_t)blockIdx.z * K * N;
    int n0 = blockIdx.x * 32, k0 = blockIdx.y * 32;
    int tx = threadIdx.x, ty = threadIdx.y;
    #pragma unroll
    for (int j = 0; j < 4; j++)
        t[ty + j * 8][tx] = ip[(size_t)(k0 + ty + j * 8) * N + n0 + tx];
    __syncthreads();
    #pragma unroll
    for (int j = 0; j < 4; j++) {
        int n = n0 + ty + j * 8;
        int nn = INTER ? (2 * (n % I) + (n / I)) : n;
        op[(size_t)nn * K + k0 + tx] = __float2half_rn(t[tx][ty + j * 8]);
    }
}

// ---------------- unified GEMM, BK=64, 3-stage cp.async (verbatim R15 core) ----------------
template <int MODE>
__global__ void __launch_bounds__(256, 2)
k_gemm(float* __restrict__ out) {
    constexpr bool GATHER = (MODE == 0 || MODE == 3);
    constexpr int KD = (MODE == 3) ? IDIM : 2048;
    extern __shared__ __align__(16) __half smem[];

    int e, m0, n_e;
    if (GATHER) {
        int ty = blockIdx.y; if (ty >= g_ntiles) return;
        e = g_tile_e[ty]; m0 = g_tile_m[ty]; n_e = g_cnt[e];
    } else { e = 0; m0 = blockIdx.y * 128; n_e = T_TOK; }
    const int off_e = GATHER ? g_off[e] : 0;
    const int rbase = off_e + m0;
    const int n0 = blockIdx.x * 128;

    const __half* Asrc =
        (MODE == 0 || MODE == 1) ? g_x16 :
        (MODE == 2) ? g_h_shared : g_h_routed;
    const __half* Bsrc =
        (MODE == 0) ? (const __half*)g_y + (size_t)e * HDIM * 2 * IDIM :
        (MODE == 1) ? g_sgu16 :
        (MODE == 2) ? g_sd16 :
                      g_wd16 + (size_t)e * HDIM * IDIM;

    const int tid = threadIdx.x, lane = tid & 31, warp = tid >> 5;
    const int warpM = warp >> 2, warpN = warp & 3;
    const int gr = lane >> 2, tg = lane & 3;

    const uint32_t aBase = (uint32_t)__cvta_generic_to_shared(smem);
    const uint32_t bBase = aBase + NSTG * STGB;

    const int r0 = tid >> 3;
    const int kc = (tid & 7) * 8;
    const __half* aptr[4];
    #pragma unroll
    for (int i = 0; i < 4; i++) {
        int r = r0 + i * 32;
        int arow;
        if (MODE == 0) {
            int lr = r, lim = n_e - m0 - 1;
            if (lr > lim) lr = lim;
            arow = g_perm_token[off_e + m0 + lr];
        } else if (MODE == 3) {
            int lr = r, lim = n_e - m0 - 1;
            if (lr > lim) lr = lim;
            arow = rbase + lr;
        } else arow = m0 + r;
        aptr[i] = Asrc + (size_t)arow * KD + kc;
    }
    const __half* bptr0 = Bsrc + (size_t)(n0 + r0) * KD + kc;
    const uint32_t adst0 = aBase + (r0 * SMS + kc) * 2;
    const uint32_t bdst0 = bBase + (r0 * SMS + kc) * 2;
    const uint32_t dstep = 32 * SMS * 2;

    auto load_stage = [&](int s, int kt) {
        #pragma unroll
        for (int i = 0; i < 4; i++)
            cp16(adst0 + i * dstep + s * STGB, aptr[i] + kt * 64);
        #pragma unroll
        for (int i = 0; i < 4; i++)
            cp16(bdst0 + i * dstep + s * STGB, bptr0 + (size_t)i * 32 * KD + kt * 64);
    };

    const uint32_t a_off = aBase + ((warpM * 64 + (lane & 15)) * SMS + (lane >> 4) * 8) * 2;
    const uint32_t b_off = bBase + ((warpN * 32 + ((lane >> 4) << 3) + (lane & 7)) * SMS
                                    + ((lane >> 3) & 1) * 8) * 2;

    float c[4][4][4];
    #pragma unroll
    for (int mi = 0; mi < 4; mi++)
        #pragma unroll
        for (int ni = 0; ni < 4; ni++)
            #pragma unroll
            for (int q = 0; q < 4; q++) c[mi][ni][q] = 0.f;

    const int KT = KD / 64;
    load_stage(0, 0); cp_commit();
    load_stage(1, 1); cp_commit();

    auto compute_tile = [&](int buf) {
        const uint32_t aB = a_off + buf * STGB;
        const uint32_t bB = b_off + buf * STGB;
        #pragma unroll
        for (int kk = 0; kk < 4; kk++) {
            uint32_t a[4][4], b[2][4];
            #pragma unroll
            for (int mi = 0; mi < 4; mi++)
                ldsm4(a[mi], aB + (mi * 16 * SMS + kk * 16) * 2);
            #pragma unroll
            for (int nip = 0; nip < 2; nip++)
                ldsm4(b[nip], bB + (nip * 16 * SMS + kk * 16) * 2);
            #pragma unroll
            for (int mi = 0; mi < 4; mi++)
                #pragma unroll
                for (int ni = 0; ni < 4; ni++)
                    mma16816(c[mi][ni], a[mi], &b[ni >> 1][(ni & 1) * 2]);
        }
    };

    for (int kt = 0; kt < KT; kt += 3) {
        #pragma unroll
        for (int u = 0; u < 3; u++) {
            if (kt + u >= KT) break;
            cp_wait<1>();
            __syncthreads();
            compute_tile(u);
            int kn = kt + u + 2;
            if (kn < KT) load_stage((u + 2) % 3, kn);
            cp_commit();
        }
    }

    const int mlim = n_e - m0;
    if (MODE == 0 || MODE == 1) {
        constexpr int INTER = (MODE == 0) ? IDIM : SIDIM;
        __half* Hout = (MODE == 0) ? g_h_routed : g_h_shared;
        const int ch0 = blockIdx.x * 64;
        #pragma unroll
        for (int mi = 0; mi < 4; mi++) {
            int mr = warpM * 64 + mi * 16 + gr;
            #pragma unroll
            for (int ni = 0; ni < 4; ni++) {
                int ch = ch0 + warpN * 16 + ni * 4 + tg;
                float h0 = siluf(c[mi][ni][0]) * c[mi][ni][1];
                float h1 = siluf(c[mi][ni][2]) * c[mi][ni][3];
                if (mr < mlim)
                    Hout[(size_t)(rbase + mr) * INTER + ch] = __float2half_rn(h0);
                if (mr + 8 < mlim)
                    Hout[(size_t)(rbase + mr + 8) * INTER + ch] = __float2half_rn(h1);
            }
        }
    } else if (MODE == 2) {
        #pragma unroll
        for (int mi = 0; mi < 4; mi++) {
            int mr = warpM * 64 + mi * 16 + gr;
            #pragma unroll
            for (int ni = 0; ni < 4; ni++) {
                int cb = n0 + warpN * 32 + ni * 8 + 2 * tg;
                *(float2*)&out[(size_t)(m0 + mr) * HDIM + cb] =
                    make_float2(c[mi][ni][0], c[mi][ni][1]);
                *(float2*)&out[(size_t)(m0 + mr + 8) * HDIM + cb] =
                    make_float2(c[mi][ni][2], c[mi][ni][3]);
            }
        }
    } else {
        __half* o16 = (__half*)g_y + (size_t)NEXP * IDIM * HDIM;
        #pragma unroll
        for (int mi = 0; mi < 4; mi++) {
            int mr = warpM * 64 + mi * 16 + gr;
            float w0 = 1.f, w1 = 1.f;
            if (mr < mlim)     w0 = g_perm_w[rbase + mr];
            if (mr + 8 < mlim) w1 = g_perm_w[rbase + mr + 8];
            #pragma unroll
            for (int ni = 0; ni < 4; ni++) {
                int cb = n0 + warpN * 32 + ni * 8 + 2 * tg;
                if (mr < mlim)
                    *(__half2*)&o16[(size_t)(rbase + mr) * HDIM + cb] =
                        __floats2half2_rn(c[mi][ni][0] * w0, c[mi][ni][1] * w0);
                if (mr + 8 < mlim)
                    *(__half2*)&o16[(size_t)(rbase + mr + 8) * HDIM + cb] =
                        __floats2half2_rn(c[mi][ni][2] * w1, c[mi][ni][3] * w1);
            }
        }
    }
}

// out[t] += sum_k o16[pos(t,k)]  (f16 inputs, f32 accumulate)
__global__ void k_combine(float* __restrict__ out) {
    __shared__ int pos8[TOPK];
    const int t = blockIdx.x;
    if (threadIdx.x < TOPK) pos8[threadIdx.x] = g_tok_pos[t * TOPK + threadIdx.x];
    __syncthreads();
    const __half* o16 = (const __half*)g_y + (size_t)NEXP * IDIM * HDIM;
    const int cbase = threadIdx.x * 8;
    float* op = out + (size_t)t * HDIM + cbase;
    float acc[8];
    #pragma unroll
    for (int j = 0; j < 8; j++) acc[j] = op[j];
    #pragma unroll
    for (int k = 0; k < TOPK; k++) {
        const __half2* yp = (const __half2*)(o16 + (size_t)pos8[k] * HDIM + cbase);
        #pragma unroll
        for (int j = 0; j < 4; j++) {
            float2 v = __half22float2(yp[j]);
            acc[2 * j]     += v.x;
            acc[2 * j + 1] += v.y;
        }
    }
    #pragma unroll
    for (int j = 0; j < 8; j++) op[j] = acc[j];
}

// ---- fork/join stream machinery ----
struct Sched {
    cudaStream_t s1 = nullptr, s2 = nullptr;
    cudaEvent_t eFork = nullptr, eWgu = nullptr, eX16 = nullptr,
                eWd = nullptr, eB = nullptr;
    bool ok = false;
    Sched() {
        ok = (cudaStreamCreateWithFlags(&s1, cudaStreamNonBlocking) == cudaSuccess)
          && (cudaStreamCreateWithFlags(&s2, cudaStreamNonBlocking) == cudaSuccess)
          && (cudaEventCreateWithFlags(&eFork, cudaEventDisableTiming) == cudaSuccess)
          && (cudaEventCreateWithFlags(&eWgu,  cudaEventDisableTiming) == cudaSuccess)
          && (cudaEventCreateWithFlags(&eX16,  cudaEventDisableTiming) == cudaSuccess)
          && (cudaEventCreateWithFlags(&eWd,   cudaEventDisableTiming) == cudaSuccess)
          && (cudaEventCreateWithFlags(&eB,    cudaEventDisableTiming) == cudaSuccess);
    }
};
static Sched g_sched;

extern "C" void kernel_launch(void* const* d_in, const int* in_sizes, int n_in,
                              void* d_out, int out_size) {
    const float* X   = (const float*)d_in[0];
    const float* GW  = (const float*)d_in[1];
    const float* GB  = (const float*)d_in[2];
    const float* WGU = (const float*)d_in[3];
    const float* WD  = (const float*)d_in[4];
    const float* SGU = (const float*)d_in[5];
    const float* SD  = (const float*)d_in[6];
    float* out = (float*)d_out;

    static int smem_set = 0;
    if (!smem_set) {
        cudaFuncSetAttribute(k_gemm<0>, cudaFuncAttributeMaxDynamicSharedMemorySize, SMEMB);
        cudaFuncSetAttribute(k_gemm<1>, cudaFuncAttributeMaxDynamicSharedMemorySize, SMEMB);
        cudaFuncSetAttribute(k_gemm<2>, cudaFuncAttributeMaxDynamicSharedMemorySize, SMEMB);
        cudaFuncSetAttribute(k_gemm<3>, cudaFuncAttributeMaxDynamicSharedMemorySize, SMEMB);
        smem_set = 1;
    }

    if (g_sched.ok) {
        cudaStream_t s0 = 0, s1 = g_sched.s1, s2 = g_sched.s2;
        cudaEventRecord(g_sched.eFork, s0);
        cudaStreamWaitEvent(s1, g_sched.eFork, 0);
        cudaStreamWaitEvent(s2, g_sched.eFork, 0);

        // s2: wd transpose now runs at fork time (own buffer, no aliasing dep)
        k_t<false, 3><<<dim3(64, 32, NEXP), dim3(32, 8), 0, s2>>>(WD, IDIM, HDIM, 0);
        cudaEventRecord(g_sched.eWd, s2);

        // s1: remaining weight transposes, then chain B GEMMs
        k_t<true, 0><<<dim3(64, 64, NEXP), dim3(32, 8), 0, s1>>>(WGU, HDIM, 2 * IDIM, IDIM);
        cudaEventRecord(g_sched.eWgu, s1);
        k_t<true, 1><<<dim3(128, 64, 1), dim3(32, 8), 0, s1>>>(SGU, HDIM, 2 * SIDIM, SIDIM);
        k_t<false, 2><<<dim3(64, 64, 1), dim3(32, 8), 0, s1>>>(SD, SIDIM, HDIM, 0);

        // s0: routing (also produces g_x16)
        k_zero<<<1, 32, 0, s0>>>();
        k_route<<<T_TOK / 16, 512, 0, s0>>>(X, GW, GB);
        cudaEventRecord(g_sched.eX16, s0);
        k_scan<<<1, 1, 0, s0>>>();
        k_perm<<<NASSIGN / 256, 256, 0, s0>>>();

        // chain A on s0: gemm0 -> gemm3 (wd16 ready long before)
        cudaStreamWaitEvent(s0, g_sched.eWgu, 0);
        k_gemm<0><<<dim3(16, MAXTILES), 256, SMEMB, s0>>>(nullptr);
        cudaStreamWaitEvent(s0, g_sched.eWd, 0);
        k_gemm<3><<<dim3(16, MAXTILES), 256, SMEMB, s0>>>(nullptr);

        // chain B on s1: gemm1 -> gemm2
        cudaStreamWaitEvent(s1, g_sched.eX16, 0);
        k_gemm<1><<<dim3(32, 32), 256, SMEMB, s1>>>(nullptr);
        k_gemm<2><<<dim3(16, 32), 256, SMEMB, s1>>>(out);
        cudaEventRecord(g_sched.eB, s1);

        // join
        cudaStreamWaitEvent(s0, g_sched.eB, 0);
        k_combine<<<T_TOK, 256, 0, s0>>>(out);
    } else {
        k_zero<<<1, 32>>>();
        k_route<<<T_TOK / 16, 512>>>(X, GW, GB);
        k_scan<<<1, 1>>>();
        k_perm<<<NASSIGN / 256, 256>>>();
        k_t<true, 0><<<dim3(64, 64, NEXP), dim3(32, 8)>>>(WGU, HDIM, 2 * IDIM, IDIM);
        k_t<true, 1><<<dim3(128, 64, 1), dim3(32, 8)>>>(SGU, HDIM, 2 * SIDIM, SIDIM);
        k_t<false, 2><<<dim3(64, 64, 1), dim3(32, 8)>>>(SD, SIDIM, HDIM, 0);
        k_t<false, 3><<<dim3(64, 32, NEXP), dim3(32, 8)>>>(WD, IDIM, HDIM, 0);
        k_gemm<0><<<dim3(16, MAXTILES), 256, SMEMB>>>(nullptr);
        k_gemm<1><<<dim3(32, 32), 256, SMEMB>>>(nullptr);
        k_gemm<2><<<dim3(16, 32), 256, SMEMB>>>(out);
        k_gemm<3><<<dim3(16, MAXTILES), 256, SMEMB>>>(nullptr);
        k_combine<<<T_TOK, 256>>>(out);
    }
}